// round 12
// baseline (speedup 1.0000x reference)
#include <cuda_runtime.h>
#include <cuda_bf16.h>
#include <cstdint>

#define EE   2048
#define CC   64
#define FF   18
#define NTOK 18432
#define KS   64
#define KCH  8       // split-K chunks in wgemm

typedef unsigned long long u64;
typedef unsigned int u32;

// Scratch (__device__ globals: allocation-free rule)
__device__ float g_part[KCH * CC * EE];                   // wgemm split-K partials (4 MB)
__device__ float g_mpart[2 * NTOK * CC];                  // main split-K partials (9.4 MB)
__device__ float g_T1[CC * EE];                           // Wmp @ Wo
__device__ float g_Mf[CC * EE];                           // 0.75 * T1 @ Wv (fp32)
__device__ __align__(16) float g_beta[CC];
__device__ int   g_scl[CC];                               // per-c abs-max of M (float bits)
__device__ float g_k1[CC];                                // per-c epilogue scale
__device__ __align__(16) unsigned char g_BQ[32 * CC * 128]; // M int8 hi|lo, swizzled per-stage

#define SXRANGE 8.0f
#define XC1 15.875f               // 127/8
#define XSTEP1 (8.0f/127.0f)
#define XC2 4064.0f               // 127*256/8

// ---------------- helpers ----------------
__device__ __forceinline__ unsigned smem_u32(const void* p) {
    return (unsigned)__cvta_generic_to_shared(p);
}
__device__ __forceinline__ void cp16(unsigned s, const void* g) {
    asm volatile("cp.async.ca.shared.global [%0], [%1], 16;" :: "r"(s), "l"(g));
}
__device__ __forceinline__ void cp_commit() { asm volatile("cp.async.commit_group;"); }
__device__ __forceinline__ void cp_wait0()  { asm volatile("cp.async.wait_group 0;"); }
__device__ __forceinline__ void sts64(u32 a, u32 lo, u32 hi) {
    asm volatile("st.shared.v2.u32 [%0], {%1,%2};" :: "r"(a), "r"(lo), "r"(hi));
}
__device__ __forceinline__ void ldsm4(u32& r0, u32& r1, u32& r2, u32& r3, u32 a) {
    asm volatile("ldmatrix.sync.aligned.m8n8.x4.shared.b16 {%0,%1,%2,%3}, [%4];"
                 : "=r"(r0), "=r"(r1), "=r"(r2), "=r"(r3) : "r"(a));
}
__device__ __forceinline__ void ldsm4t(u32& r0, u32& r1, u32& r2, u32& r3, u32 a) {
    asm volatile("ldmatrix.sync.aligned.m8n8.x4.trans.shared.b16 {%0,%1,%2,%3}, [%4];"
                 : "=r"(r0), "=r"(r1), "=r"(r2), "=r"(r3) : "r"(a));
}
__device__ __forceinline__ void mma16816(float* c, u32 a0, u32 a1, u32 a2, u32 a3,
                                         u32 b0, u32 b1) {
    asm volatile("mma.sync.aligned.m16n8k16.row.col.f32.bf16.bf16.f32 "
                 "{%0,%1,%2,%3}, {%4,%5,%6,%7}, {%8,%9}, {%0,%1,%2,%3};"
                 : "+f"(c[0]), "+f"(c[1]), "+f"(c[2]), "+f"(c[3])
                 : "r"(a0), "r"(a1), "r"(a2), "r"(a3), "r"(b0), "r"(b1));
}
__device__ __forceinline__ void imma(int* c, u32 a0, u32 a1, u32 a2, u32 a3,
                                     u32 b0, u32 b1) {
    asm volatile("mma.sync.aligned.m16n8k32.row.col.s32.s8.s8.s32 "
                 "{%0,%1,%2,%3}, {%4,%5,%6,%7}, {%8,%9}, {%0,%1,%2,%3};"
                 : "+r"(c[0]), "+r"(c[1]), "+r"(c[2]), "+r"(c[3])
                 : "r"(a0), "r"(a1), "r"(a2), "r"(a3), "r"(b0), "r"(b1));
}
__device__ __forceinline__ u32 swz(u32 off) { return off ^ ((off >> 3) & 0x70u); }
__device__ __forceinline__ u32 prmtf(u32 a, u32 b, u32 s) {
    u32 d; asm("prmt.b32 %0, %1, %2, %3;" : "=r"(d) : "r"(a), "r"(b), "r"(s)); return d;
}
__device__ __forceinline__ u32 pack4(int q0, int q1, int q2, int q3) {
    u32 r01 = prmtf((u32)q0, (u32)q1, 0x0040u);
    u32 r23 = prmtf((u32)q2, (u32)q3, 0x0040u);
    return prmtf(r01, r23, 0x5410u);
}

__device__ __forceinline__ void split4(float4 v, u32& h01, u32& h23, u32& l01, u32& l23) {
    asm("cvt.rn.bf16x2.f32 %0, %1, %2;" : "=r"(h01) : "f"(v.y), "f"(v.x));
    asm("cvt.rn.bf16x2.f32 %0, %1, %2;" : "=r"(h23) : "f"(v.w), "f"(v.z));
    float e0 = v.x - __uint_as_float(h01 << 16);
    float e1 = v.y - __uint_as_float(h01 & 0xffff0000u);
    float e2 = v.z - __uint_as_float(h23 << 16);
    float e3 = v.w - __uint_as_float(h23 & 0xffff0000u);
    asm("cvt.rn.bf16x2.f32 %0, %1, %2;" : "=r"(l01) : "f"(e1), "f"(e0));
    asm("cvt.rn.bf16x2.f32 %0, %1, %2;" : "=r"(l23) : "f"(e3), "f"(e2));
}

// int8 hi/lo quantization of 4 floats with scale pair (c1 = 1/step1, c2 = 256/step1)
__device__ __forceinline__ void quant4(float4 v, float c1, float step1, float c2,
                                       u32& hq, u32& lq) {
    float h0 = fminf(fmaxf(rintf(v.x * c1), -127.f), 127.f);
    float h1 = fminf(fmaxf(rintf(v.y * c1), -127.f), 127.f);
    float h2 = fminf(fmaxf(rintf(v.z * c1), -127.f), 127.f);
    float h3 = fminf(fmaxf(rintf(v.w * c1), -127.f), 127.f);
    float r0 = fmaf(h0, -step1, v.x);
    float r1 = fmaf(h1, -step1, v.y);
    float r2 = fmaf(h2, -step1, v.z);
    float r3 = fmaf(h3, -step1, v.w);
    float l0 = fminf(fmaxf(rintf(r0 * c2), -127.f), 127.f);
    float l1 = fminf(fmaxf(rintf(r1 * c2), -127.f), 127.f);
    float l2 = fminf(fmaxf(rintf(r2 * c2), -127.f), 127.f);
    float l3 = fminf(fmaxf(rintf(r3 * c2), -127.f), 127.f);
    hq = pack4((int)h0, (int)h1, (int)h2, (int)h3);
    lq = pack4((int)l0, (int)l1, (int)l2, (int)l3);
}

// ---------------------------------------------------------------------------
// wgemm (split-K, bf16 3-term) — unchanged from round 11 (proven).
// ---------------------------------------------------------------------------
__global__ void __launch_bounds__(256, 2)
wgemm(const float* __restrict__ Aglob, const float* __restrict__ Bglob, int useT1)
{
    const float* A = useT1 ? g_T1 : Aglob;
    extern __shared__ char smraw[];
    const u32 base = (smem_u32(smraw) + 1023u) & ~1023u;
    const u32 AH[2]  = { base,          base + 8192u  };
    const u32 AL[2]  = { base + 16384u, base + 24576u };
    const u32 BSH[2] = { base + 32768u, base + 40960u };
    const u32 BSL[2] = { base + 49152u, base + 57344u };

    const int tid = threadIdx.x;
    const int wid = tid >> 5, lane = tid & 31;
    const int j0 = blockIdx.x * 64;
    const int kbase = blockIdx.y * 256;
    const int c0 = (wid & 3) * 16;
    const int jh = (wid >> 2) * 32;

    const int lr = tid >> 4;
    const int lc = tid & 15;

    float acc[4][4];
#pragma unroll
    for (int i = 0; i < 4; ++i)
#pragma unroll
        for (int j = 0; j < 4; ++j) acc[i][j] = 0.f;

    float4 rA[4], rB[4];
#pragma unroll
    for (int i = 0; i < 4; ++i) {
        rA[i] = *(const float4*)(A + (size_t)(lr + 16 * i) * EE + kbase + lc * 4);
        rB[i] = *(const float4*)(Bglob + (size_t)(kbase + lr + 16 * i) * EE + j0 + lc * 4);
    }

    for (int t = 0; t < 4; ++t) {
        const int buf = t & 1;
#pragma unroll
        for (int i = 0; i < 4; ++i) {
            const u32 sw = swz((u32)((lr + 16 * i) * 128 + lc * 8));
            u32 h01, h23, l01, l23;
            split4(rA[i], h01, h23, l01, l23);
            sts64(AH[buf] + sw, h01, h23);
            sts64(AL[buf] + sw, l01, l23);
            split4(rB[i], h01, h23, l01, l23);
            sts64(BSH[buf] + sw, h01, h23);
            sts64(BSL[buf] + sw, l01, l23);
        }
        __syncthreads();

        if (t + 1 < 4) {
            const int kc = kbase + (t + 1) * 64;
#pragma unroll
            for (int i = 0; i < 4; ++i) {
                rA[i] = *(const float4*)(A + (size_t)(lr + 16 * i) * EE + kc + lc * 4);
                rB[i] = *(const float4*)(Bglob + (size_t)(kc + lr + 16 * i) * EE + j0 + lc * 4);
            }
        }

        const int r = lane & 7, g = lane >> 3;
#pragma unroll
        for (int s = 0; s < 4; ++s) {
            const u32 asw = swz((u32)((c0 + (lane & 15)) * 128 + s * 32 + (lane >> 4) * 16));
            u32 a0, a1, a2, a3, f0, f1, f2, f3;
            ldsm4(a0, a1, a2, a3, AH[buf] + asw);
            ldsm4(f0, f1, f2, f3, AL[buf] + asw);
#pragma unroll
            for (int h = 0; h < 2; ++h) {
                const int jb = jh + h * 16;
                const u32 bsw = swz((u32)((s * 16 + (g >> 1) * 8 + r) * 128
                                          + (jb + (g & 1) * 8) * 2));
                u32 b0, b1, b2, b3, e0, e1, e2, e3;
                ldsm4t(b0, b1, b2, b3, BSH[buf] + bsw);
                ldsm4t(e0, e1, e2, e3, BSL[buf] + bsw);
                mma16816(acc[2 * h],     a0, a1, a2, a3, b0, b2);
                mma16816(acc[2 * h],     a0, a1, a2, a3, e0, e2);
                mma16816(acc[2 * h],     f0, f1, f2, f3, b0, b2);
                mma16816(acc[2 * h + 1], a0, a1, a2, a3, b1, b3);
                mma16816(acc[2 * h + 1], a0, a1, a2, a3, e1, e3);
                mma16816(acc[2 * h + 1], f0, f1, f2, f3, b1, b3);
            }
        }
        if (t + 1 < 4) __syncthreads();
    }

    const int r0 = lane >> 2;
    const int cb = 2 * (lane & 3);
    float* pbase = g_part + (size_t)blockIdx.y * (CC * EE);
#pragma unroll
    for (int nt = 0; nt < 4; ++nt) {
        const int j = j0 + jh + nt * 8 + cb;
        const int ca = c0 + r0, cbig = ca + 8;
        *(float2*)&pbase[(size_t)ca * EE + j]   = make_float2(acc[nt][0], acc[nt][1]);
        *(float2*)&pbase[(size_t)cbig * EE + j] = make_float2(acc[nt][2], acc[nt][3]);
    }
}

// ---------------------------------------------------------------------------
// reduceK: sum KCH partials (float4/thread).
// which==0 -> g_T1 (fp32) and zero g_scl.
// which==1 -> 0.75x into g_Mf + per-c abs-max into g_scl (block reduce + atomicMax).
// ---------------------------------------------------------------------------
__global__ void reduceK(int which)
{
    const int tid = threadIdx.x;
    if (which == 0 && blockIdx.x == 0 && tid < CC) g_scl[tid] = 0;

    const int i4 = blockIdx.x * 256 + tid;  // 0 .. 32767
    float4 s = make_float4(0.f, 0.f, 0.f, 0.f);
#pragma unroll
    for (int q = 0; q < KCH; ++q) {
        float4 v = *(const float4*)&g_part[(size_t)q * (CC * EE) + i4 * 4];
        s.x += v.x; s.y += v.y; s.z += v.z; s.w += v.w;
    }
    if (which == 0) {
        *(float4*)&g_T1[i4 * 4] = s;
    } else {
        s.x *= 0.75f; s.y *= 0.75f; s.z *= 0.75f; s.w *= 0.75f;
        *(float4*)&g_Mf[i4 * 4] = s;
        // block covers exactly half of one c row (512 i4 per c, 256 per block)
        __shared__ float red[256];
        float m = fmaxf(fmaxf(fabsf(s.x), fabsf(s.y)), fmaxf(fabsf(s.z), fabsf(s.w)));
        red[tid] = m;
        __syncthreads();
#pragma unroll
        for (int o = 128; o >= 32; o >>= 1) {
            if (tid < o) red[tid] = fmaxf(red[tid], red[tid + o]);
            __syncthreads();
        }
        if (tid < 32) {
            float v = red[tid];
#pragma unroll
            for (int o = 16; o; o >>= 1)
                v = fmaxf(v, __shfl_xor_sync(0xffffffffu, v, o));
            if (tid == 0) {
                const int c = (blockIdx.x * 256) >> 9;   // i4>>9
                atomicMax(&g_scl[c], __float_as_int(v)); // positive floats: int order ok
            }
        }
    }
}

// ---------------------------------------------------------------------------
// quantM: per-c int8 hi/lo split of g_Mf into g_BQ (pre-swizzled [hi64|lo64] rows)
// and epilogue scale g_k1[c] = (8/127)*(SM_c/127).
// 64 blocks (one per c) x 256 threads (8 elements each).
// ---------------------------------------------------------------------------
__global__ void quantM()
{
    const int c = blockIdx.x, tid = threadIdx.x;
    const float SM = __int_as_float(g_scl[c]);
    const float s1 = SM / 127.f;
    const float c1 = 127.f / SM;
    const float c2 = c1 * 256.f;
    if (tid == 0) g_k1[c] = (8.f / 127.f) * s1;

#pragma unroll
    for (int q = 0; q < 2; ++q) {
        const int k4 = tid + 256 * q;          // float4 index, k = k4*4
        float4 v = *(const float4*)&g_Mf[(size_t)c * EE + k4 * 4];
        u32 hq, lq;
        quant4(v, c1, s1, c2, hq, lq);
        const int k = k4 * 4;
        const int stage = k >> 6, kk = k & 63;
        *(u32*)(g_BQ + (size_t)stage * 8192 + swz((u32)(c * 128 + kk)))      = hq;
        *(u32*)(g_BQ + (size_t)stage * 8192 + swz((u32)(c * 128 + 64 + kk))) = lq;
    }
}

// ---------------------------------------------------------------------------
// Beta fold: beta[c] = 0.75*(T1[c,:]@bv + Wmp[c,:]@bo) + bmp[c]
// ---------------------------------------------------------------------------
__global__ void k_beta2(const float* __restrict__ bv, const float* __restrict__ bo,
                        const float* __restrict__ bmp, const float* __restrict__ Wmp)
{
    __shared__ float red[256];
    const int c = blockIdx.x, tid = threadIdx.x;
    const float4* t1r = (const float4*)(g_T1 + (size_t)c * EE);
    const float4* wmr = (const float4*)(Wmp + (size_t)c * EE);
    const float4* bv4 = (const float4*)bv;
    const float4* bo4 = (const float4*)bo;
    float s = 0.f;
#pragma unroll
    for (int q = 0; q < 2; ++q) {
        const int i = tid + 256 * q;
        float4 a = t1r[i], b = bv4[i], d = wmr[i], e = bo4[i];
        s += a.x * b.x + a.y * b.y + a.z * b.z + a.w * b.w;
        s += d.x * e.x + d.y * e.y + d.z * e.z + d.w * e.w;
    }
    red[tid] = s;
    __syncthreads();
#pragma unroll
    for (int o = 128; o >= 32; o >>= 1) {
        if (tid < o) red[tid] += red[tid + o];
        __syncthreads();
    }
    if (tid < 32) {
        float v = red[tid];
#pragma unroll
        for (int o = 16; o; o >>= 1) v += __shfl_xor_sync(0xffffffffu, v, o);
        if (tid == 0) g_beta[c] = 0.75f * v + bmp[c];
    }
}

// ---------------------------------------------------------------------------
// Main GEMM int8 split-K: grid (144 token-tiles, 2 k-halves), 256 threads.
// out_partial[n,c] = (HH + CX/256) * k1_c where
//   HH = sum qh(x)*mh, CX = sum (qh*ml + ql*mh)  via mma.m16n8k32.s8 (48/stage
//   vs 96 HMMA before). Smem rows: 128 B = [hi 64B | lo 64B], same SW128 swizzle.
// ---------------------------------------------------------------------------
__global__ void __launch_bounds__(256, 2)
main_int8(const float* __restrict__ x)
{
    extern __shared__ char smraw[];
    const u32 base = (smem_u32(smraw) + 1023u) & ~1023u;
    const u32 XQ[2] = { base,          base + 16384u };
    const u32 BQ[2] = { base + 32768u, base + 40960u };

    const int tid = threadIdx.x;
    const int wid = tid >> 5, lane = tid & 31;
    const int n0 = blockIdx.x * 128;
    const int kh = blockIdx.y;
    const int kbase = kh * 1024;
    const int m0 = wid * 16;

    int hh[8][4], cx[8][4];
#pragma unroll
    for (int i = 0; i < 8; ++i)
#pragma unroll
        for (int j = 0; j < 4; ++j) { hh[i][j] = 0; cx[i][j] = 0; }

    const int xr = tid >> 4, xc4 = tid & 15;

    float4 ra[8];
#pragma unroll
    for (int i = 0; i < 8; ++i)
        ra[i] = *(const float4*)(x + (size_t)(n0 + xr + 16 * i) * EE + kbase + xc4 * 4);
    {
        const char* sb = (const char*)g_BQ + (size_t)(kh * 16) * 8192 + tid * 32;
        cp16(BQ[0] + (u32)tid * 32,      sb);
        cp16(BQ[0] + (u32)tid * 32 + 16, sb + 16);
        cp_commit();
    }

    for (int t = 0; t < 16; ++t) {
        const int buf = t & 1;
        cp_wait0();

        // quantize & store X chunk t ([hi|lo] int8 rows, swizzled)
#pragma unroll
        for (int i = 0; i < 8; ++i) {
            u32 hq, lq;
            quant4(ra[i], XC1, XSTEP1, XC2, hq, lq);
            const u32 rb = (u32)((xr + 16 * i) * 128);
            asm volatile("st.shared.u32 [%0], %1;"
                         :: "r"(XQ[buf] + swz(rb + xc4 * 4)), "r"(hq));
            asm volatile("st.shared.u32 [%0], %1;"
                         :: "r"(XQ[buf] + swz(rb + 64 + xc4 * 4)), "r"(lq));
        }
        __syncthreads();

        // issue next-stage B cp.async + X LDG prefetch (overlap with MMA)
        if (t + 1 < 16) {
            const char* sb = (const char*)g_BQ + (size_t)(kh * 16 + t + 1) * 8192 + tid * 32;
            cp16(BQ[buf ^ 1] + (u32)tid * 32,      sb);
            cp16(BQ[buf ^ 1] + (u32)tid * 32 + 16, sb + 16);
            cp_commit();
            const int k0 = kbase + (t + 1) * KS;
#pragma unroll
            for (int i = 0; i < 8; ++i)
                ra[i] = *(const float4*)(x + (size_t)(n0 + xr + 16 * i) * EE + k0 + xc4 * 4);
        }

        // IMMA over chunk t (2 x k32 steps), term-outermost
#pragma unroll
        for (int s = 0; s < 2; ++s) {
            const u32 arow = (u32)((m0 + (lane & 15)) * 128);
            const u32 koff = (u32)(s * 32 + (lane >> 4) * 16);
            u32 a0, a1, a2, a3, f0, f1, f2, f3;
            ldsm4(a0, a1, a2, a3, XQ[buf] + swz(arow + koff));        // X hi
            ldsm4(f0, f1, f2, f3, XQ[buf] + swz(arow + 64 + koff));   // X lo

            // pass 1: qh*mh -> HH
#pragma unroll
            for (int j = 0; j < 4; ++j) {
                const u32 brow = (u32)((16 * j + (lane & 15)) * 128);
                u32 b0, b1, b2, b3;
                ldsm4(b0, b1, b2, b3, BQ[buf] + swz(brow + koff));
                imma(hh[2 * j],     a0, a1, a2, a3, b0, b2);
                imma(hh[2 * j + 1], a0, a1, a2, a3, b1, b3);
            }
            // pass 2: ql*mh -> CX
#pragma unroll
            for (int j = 0; j < 4; ++j) {
                const u32 brow = (u32)((16 * j + (lane & 15)) * 128);
                u32 b0, b1, b2, b3;
                ldsm4(b0, b1, b2, b3, BQ[buf] + swz(brow + koff));
                imma(cx[2 * j],     f0, f1, f2, f3, b0, b2);
                imma(cx[2 * j + 1], f0, f1, f2, f3, b1, b3);
            }
            // pass 3: qh*ml -> CX
#pragma unroll
            for (int j = 0; j < 4; ++j) {
                const u32 brow = (u32)((16 * j + (lane & 15)) * 128);
                u32 b0, b1, b2, b3;
                ldsm4(b0, b1, b2, b3, BQ[buf] + swz(brow + 64 + koff));
                imma(cx[2 * j],     a0, a1, a2, a3, b0, b2);
                imma(cx[2 * j + 1], a0, a1, a2, a3, b1, b3);
            }
        }
    }

    // Epilogue: scale and write fp32 partials [half][n][c]
    const int r0 = lane >> 2;
    const int cb = 2 * (lane & 3);
    const int na = n0 + m0 + r0;
    float* pa = g_mpart + ((size_t)kh * NTOK + na) * CC;
    float* pb = pa + 8 * CC;
#pragma unroll
    for (int nt = 0; nt < 8; ++nt) {
        const int c = 8 * nt + cb;
        const float k1a = g_k1[c], k1b = g_k1[c + 1];
        float2 w0, w1;
        w0.x = ((float)hh[nt][0] + (float)cx[nt][0] * 0.00390625f) * k1a;
        w0.y = ((float)hh[nt][1] + (float)cx[nt][1] * 0.00390625f) * k1b;
        w1.x = ((float)hh[nt][2] + (float)cx[nt][2] * 0.00390625f) * k1a;
        w1.y = ((float)hh[nt][3] + (float)cx[nt][3] * 0.00390625f) * k1b;
        *(float2*)(pa + c) = w0;
        *(float2*)(pb + c) = w1;
    }
}

// ---------------------------------------------------------------------------
// Combine (float4): out[p, t, c..c+3] = part0 + part1 + beta,  n = t*1024+p
// ---------------------------------------------------------------------------
__global__ void combine(float* __restrict__ out)
{
    const int e4 = blockIdx.x * 256 + threadIdx.x;   // 0 .. NTOK*CC/4-1
    const int n = e4 >> 4, c = (e4 & 15) * 4;
    const float4 a = *(const float4*)&g_mpart[(size_t)n * CC + c];
    const float4 b = *(const float4*)&g_mpart[(size_t)(NTOK + n) * CC + c];
    const float4 bb = *(const float4*)&g_beta[c];
    float4 w;
    w.x = a.x + b.x + bb.x; w.y = a.y + b.y + bb.y;
    w.z = a.z + b.z + bb.z; w.w = a.w + b.w + bb.w;
    const int p = n & 1023, t = n >> 10;
    *(float4*)&out[(size_t)p * (FF * CC) + t * CC + c] = w;
}

// ---------------------------------------------------------------------------
extern "C" void kernel_launch(void* const* d_in, const int* in_sizes, int n_in,
                              void* d_out, int out_size)
{
    (void)in_sizes; (void)n_in; (void)out_size;
    const float* emb = (const float*)d_in[0];
    const float* Wv  = (const float*)d_in[3];
    const float* bv  = (const float*)d_in[6];
    const float* Wo  = (const float*)d_in[7];
    const float* bo  = (const float*)d_in[8];
    const float* Wmp = (const float*)d_in[9];
    const float* bmp = (const float*)d_in[10];
    float* out = (float*)d_out;

    const int wg_smem = 65536 + 1024;
    const int mi_smem = 49152 + 1024;
    cudaFuncSetAttribute(wgemm, cudaFuncAttributeMaxDynamicSharedMemorySize, wg_smem);
    cudaFuncSetAttribute(main_int8, cudaFuncAttributeMaxDynamicSharedMemorySize, mi_smem);

    // T1 = Wmp @ Wo (split-K over full chip), reduce (+zero scales)
    wgemm<<<dim3(32, KCH), 256, wg_smem>>>(Wmp, Wo, 0);
    reduceK<<<128, 256>>>(0);
    // M = 0.75 * T1 @ Wv: reduce -> fp32 M + per-c scales -> int8 split tiles
    wgemm<<<dim3(32, KCH), 256, wg_smem>>>(nullptr, Wv, 1);
    reduceK<<<128, 256>>>(1);
    quantM<<<64, 256>>>();
    k_beta2<<<64, 256>>>(bv, bo, bmp, Wmp);

    // Main GEMM int8 split-K (2 CTAs/SM) + combine epilogue
    main_int8<<<dim3(144, 2), 256, mi_smem>>>(emb);
    combine<<<(NTOK * CC) / 4 / 256, 256>>>(out);
}

// round 13
// speedup vs baseline: 1.7856x; 1.7856x over previous
#include <cuda_runtime.h>
#include <cuda_bf16.h>
#include <cstdint>

#define EE   2048
#define CC   64
#define FF   18
#define NTOK 18432
#define KS   64
#define KCH  8       // split-K chunks in wgemm

typedef unsigned long long u64;
typedef unsigned int u32;

// Scratch (__device__ globals: allocation-free rule)
__device__ float g_part[KCH * CC * EE];                   // wgemm split-K partials (4 MB)
__device__ float g_mpart[2 * NTOK * CC];                  // main split-K partials (9.4 MB)
__device__ float g_T1[CC * EE];                           // Wmp @ Wo
__device__ __align__(16) float g_beta[CC];
__device__ __align__(16) unsigned char g_Bh[CC * EE * 2]; // M hi, pre-swizzled per-stage tiles
__device__ __align__(16) unsigned char g_Bl[CC * EE * 2]; // M lo, pre-swizzled per-stage tiles

// ---------------- helpers ----------------
__device__ __forceinline__ unsigned smem_u32(const void* p) {
    return (unsigned)__cvta_generic_to_shared(p);
}
__device__ __forceinline__ void cp16(unsigned s, const void* g) {
    asm volatile("cp.async.ca.shared.global [%0], [%1], 16;" :: "r"(s), "l"(g));
}
__device__ __forceinline__ void cp_commit() { asm volatile("cp.async.commit_group;"); }
__device__ __forceinline__ void cp_wait0()  { asm volatile("cp.async.wait_group 0;"); }
__device__ __forceinline__ void sts64(u32 a, u32 lo, u32 hi) {
    asm volatile("st.shared.v2.u32 [%0], {%1,%2};" :: "r"(a), "r"(lo), "r"(hi));
}
__device__ __forceinline__ void ldsm4(u32& r0, u32& r1, u32& r2, u32& r3, u32 a) {
    asm volatile("ldmatrix.sync.aligned.m8n8.x4.shared.b16 {%0,%1,%2,%3}, [%4];"
                 : "=r"(r0), "=r"(r1), "=r"(r2), "=r"(r3) : "r"(a));
}
__device__ __forceinline__ void ldsm4t(u32& r0, u32& r1, u32& r2, u32& r3, u32 a) {
    asm volatile("ldmatrix.sync.aligned.m8n8.x4.trans.shared.b16 {%0,%1,%2,%3}, [%4];"
                 : "=r"(r0), "=r"(r1), "=r"(r2), "=r"(r3) : "r"(a));
}
__device__ __forceinline__ void mma16816(float* c, u32 a0, u32 a1, u32 a2, u32 a3,
                                         u32 b0, u32 b1) {
    asm volatile("mma.sync.aligned.m16n8k16.row.col.f32.bf16.bf16.f32 "
                 "{%0,%1,%2,%3}, {%4,%5,%6,%7}, {%8,%9}, {%0,%1,%2,%3};"
                 : "+f"(c[0]), "+f"(c[1]), "+f"(c[2]), "+f"(c[3])
                 : "r"(a0), "r"(a1), "r"(a2), "r"(a3), "r"(b0), "r"(b1));
}
__device__ __forceinline__ u32 swz(u32 off) { return off ^ ((off >> 3) & 0x70u); }

__device__ __forceinline__ void split4(float4 v, u32& h01, u32& h23, u32& l01, u32& l23) {
    asm("cvt.rn.bf16x2.f32 %0, %1, %2;" : "=r"(h01) : "f"(v.y), "f"(v.x));
    asm("cvt.rn.bf16x2.f32 %0, %1, %2;" : "=r"(h23) : "f"(v.w), "f"(v.z));
    float e0 = v.x - __uint_as_float(h01 << 16);
    float e1 = v.y - __uint_as_float(h01 & 0xffff0000u);
    float e2 = v.z - __uint_as_float(h23 << 16);
    float e3 = v.w - __uint_as_float(h23 & 0xffff0000u);
    asm("cvt.rn.bf16x2.f32 %0, %1, %2;" : "=r"(l01) : "f"(e1), "f"(e0));
    asm("cvt.rn.bf16x2.f32 %0, %1, %2;" : "=r"(l23) : "f"(e3), "f"(e2));
}

// ---------------------------------------------------------------------------
// wgemm (split-K): partial[kc][c][j] = sum_{k in chunk kc} A[c,k] * B[k,j]
// grid = (32 j-tiles of 64, 8 k-chunks of 256); 4 double-buffered stages.
// ---------------------------------------------------------------------------
__global__ void __launch_bounds__(256, 2)
wgemm(const float* __restrict__ Aglob, const float* __restrict__ Bglob, int useT1)
{
    const float* A = useT1 ? g_T1 : Aglob;
    extern __shared__ char smraw[];
    const u32 base = (smem_u32(smraw) + 1023u) & ~1023u;
    const u32 AH[2]  = { base,          base + 8192u  };
    const u32 AL[2]  = { base + 16384u, base + 24576u };
    const u32 BSH[2] = { base + 32768u, base + 40960u };
    const u32 BSL[2] = { base + 49152u, base + 57344u };

    const int tid = threadIdx.x;
    const int wid = tid >> 5, lane = tid & 31;
    const int j0 = blockIdx.x * 64;
    const int kbase = blockIdx.y * 256;
    const int c0 = (wid & 3) * 16;
    const int jh = (wid >> 2) * 32;

    const int lr = tid >> 4;
    const int lc = tid & 15;

    float acc[4][4];
#pragma unroll
    for (int i = 0; i < 4; ++i)
#pragma unroll
        for (int j = 0; j < 4; ++j) acc[i][j] = 0.f;

    float4 rA[4], rB[4];
#pragma unroll
    for (int i = 0; i < 4; ++i) {
        rA[i] = *(const float4*)(A + (size_t)(lr + 16 * i) * EE + kbase + lc * 4);
        rB[i] = *(const float4*)(Bglob + (size_t)(kbase + lr + 16 * i) * EE + j0 + lc * 4);
    }

    for (int t = 0; t < 4; ++t) {
        const int buf = t & 1;
#pragma unroll
        for (int i = 0; i < 4; ++i) {
            const u32 sw = swz((u32)((lr + 16 * i) * 128 + lc * 8));
            u32 h01, h23, l01, l23;
            split4(rA[i], h01, h23, l01, l23);
            sts64(AH[buf] + sw, h01, h23);
            sts64(AL[buf] + sw, l01, l23);
            split4(rB[i], h01, h23, l01, l23);
            sts64(BSH[buf] + sw, h01, h23);
            sts64(BSL[buf] + sw, l01, l23);
        }
        __syncthreads();

        if (t + 1 < 4) {
            const int kc = kbase + (t + 1) * 64;
#pragma unroll
            for (int i = 0; i < 4; ++i) {
                rA[i] = *(const float4*)(A + (size_t)(lr + 16 * i) * EE + kc + lc * 4);
                rB[i] = *(const float4*)(Bglob + (size_t)(kc + lr + 16 * i) * EE + j0 + lc * 4);
            }
        }

        const int r = lane & 7, g = lane >> 3;
#pragma unroll
        for (int s = 0; s < 4; ++s) {
            const u32 asw = swz((u32)((c0 + (lane & 15)) * 128 + s * 32 + (lane >> 4) * 16));
            u32 a0, a1, a2, a3, f0, f1, f2, f3;
            ldsm4(a0, a1, a2, a3, AH[buf] + asw);
            ldsm4(f0, f1, f2, f3, AL[buf] + asw);
#pragma unroll
            for (int h = 0; h < 2; ++h) {
                const int jb = jh + h * 16;
                const u32 bsw = swz((u32)((s * 16 + (g >> 1) * 8 + r) * 128
                                          + (jb + (g & 1) * 8) * 2));
                u32 b0, b1, b2, b3, e0, e1, e2, e3;
                ldsm4t(b0, b1, b2, b3, BSH[buf] + bsw);
                ldsm4t(e0, e1, e2, e3, BSL[buf] + bsw);
                mma16816(acc[2 * h],     a0, a1, a2, a3, b0, b2);
                mma16816(acc[2 * h],     a0, a1, a2, a3, e0, e2);
                mma16816(acc[2 * h],     f0, f1, f2, f3, b0, b2);
                mma16816(acc[2 * h + 1], a0, a1, a2, a3, b1, b3);
                mma16816(acc[2 * h + 1], a0, a1, a2, a3, e1, e3);
                mma16816(acc[2 * h + 1], f0, f1, f2, f3, b1, b3);
            }
        }
        if (t + 1 < 4) __syncthreads();
    }

    const int r0 = lane >> 2;
    const int cb = 2 * (lane & 3);
    float* pbase = g_part + (size_t)blockIdx.y * (CC * EE);
#pragma unroll
    for (int nt = 0; nt < 4; ++nt) {
        const int j = j0 + jh + nt * 8 + cb;
        const int ca = c0 + r0, cbig = ca + 8;
        *(float2*)&pbase[(size_t)ca * EE + j]   = make_float2(acc[nt][0], acc[nt][1]);
        *(float2*)&pbase[(size_t)cbig * EE + j] = make_float2(acc[nt][2], acc[nt][3]);
    }
}

// ---------------------------------------------------------------------------
// reduceK: blocks 0..127 sum KCH split-K partials (float4 per thread).
//   which==0 -> g_T1 (fp32); which==1 -> 0.75x, bf16 hi/lo, pre-swizzled.
// Mode 1 additionally runs blocks 128..191 computing beta in parallel:
//   beta[c] = 0.75*(T1[c,:]@bv + Wmp[c,:]@bo) + bmp[c]
// ---------------------------------------------------------------------------
__global__ void reduceK(int which, const float* __restrict__ bv,
                        const float* __restrict__ bo, const float* __restrict__ bmp,
                        const float* __restrict__ Wmp)
{
    const int tid = threadIdx.x;
    if (blockIdx.x >= 128) {            // beta blocks (mode 1 only)
        __shared__ float red[256];
        const int c = blockIdx.x - 128;
        const float4* t1r = (const float4*)(g_T1 + (size_t)c * EE);
        const float4* wmr = (const float4*)(Wmp + (size_t)c * EE);
        const float4* bv4 = (const float4*)bv;
        const float4* bo4 = (const float4*)bo;
        float s = 0.f;
#pragma unroll
        for (int q = 0; q < 2; ++q) {
            const int i = tid + 256 * q;
            float4 a = t1r[i], b = bv4[i], d = wmr[i], e = bo4[i];
            s += a.x * b.x + a.y * b.y + a.z * b.z + a.w * b.w;
            s += d.x * e.x + d.y * e.y + d.z * e.z + d.w * e.w;
        }
        red[tid] = s;
        __syncthreads();
#pragma unroll
        for (int o = 128; o >= 32; o >>= 1) {
            if (tid < o) red[tid] += red[tid + o];
            __syncthreads();
        }
        if (tid < 32) {
            float v = red[tid];
#pragma unroll
            for (int o = 16; o; o >>= 1) v += __shfl_xor_sync(0xffffffffu, v, o);
            if (tid == 0) g_beta[c] = 0.75f * v + bmp[c];
        }
        return;
    }

    const int i4 = blockIdx.x * 256 + tid;  // 0 .. 32767
    float4 s = make_float4(0.f, 0.f, 0.f, 0.f);
#pragma unroll
    for (int q = 0; q < KCH; ++q) {
        float4 v = *(const float4*)&g_part[(size_t)q * (CC * EE) + i4 * 4];
        s.x += v.x; s.y += v.y; s.z += v.z; s.w += v.w;
    }
    if (which == 0) {
        *(float4*)&g_T1[i4 * 4] = s;
    } else {
        s.x *= 0.75f; s.y *= 0.75f; s.z *= 0.75f; s.w *= 0.75f;
        u32 h01, h23, l01, l23;
        split4(s, h01, h23, l01, l23);
        const int i = i4 * 4;
        const int c = i >> 11, k = i & 2047;
        const int stage = k >> 6, kk = k & 63;
        const u32 sw = swz((u32)(c * 128 + kk * 2));
        *(u32*)(g_Bh + (size_t)stage * 8192 + sw)     = h01;
        *(u32*)(g_Bh + (size_t)stage * 8192 + sw + 4) = h23;
        *(u32*)(g_Bl + (size_t)stage * 8192 + sw)     = l01;
        *(u32*)(g_Bl + (size_t)stage * 8192 + sw + 4) = l23;
    }
}

// ---------------------------------------------------------------------------
// Main GEMM split-K: grid (144 token-tiles, 2 k-halves), 256 threads, occ 2.
// Term-outermost MMA ordering (round-11 champion).
// ---------------------------------------------------------------------------
__global__ void __launch_bounds__(256, 2)
main_mma_sk(const float* __restrict__ x)
{
    extern __shared__ char smraw[];
    const u32 base = (smem_u32(smraw) + 1023u) & ~1023u;
    const u32 XH[2] = { base,          base + 16384u };
    const u32 XL[2] = { base + 32768u, base + 49152u };
    const u32 BH[2] = { base + 65536u, base + 73728u };
    const u32 BL[2] = { base + 81920u, base + 90112u };

    const int tid = threadIdx.x;
    const int wid = tid >> 5, lane = tid & 31;
    const int n0 = blockIdx.x * 128;
    const int kh = blockIdx.y;
    const int kbase = kh * 1024;
    const int m0 = wid * 16;

    float acc[8][4];
#pragma unroll
    for (int i = 0; i < 8; ++i)
#pragma unroll
        for (int j = 0; j < 4; ++j) acc[i][j] = 0.f;

    const int xr = tid >> 4, xc4 = tid & 15;

    float4 ra[8];
#pragma unroll
    for (int i = 0; i < 8; ++i)
        ra[i] = *(const float4*)(x + (size_t)(n0 + xr + 16 * i) * EE + kbase + xc4 * 4);
    {
        const char* sh = (const char*)g_Bh + (size_t)(kh * 16) * 8192 + tid * 32;
        const char* sl = (const char*)g_Bl + (size_t)(kh * 16) * 8192 + tid * 32;
        cp16(BH[0] + (u32)tid * 32,      sh);
        cp16(BH[0] + (u32)tid * 32 + 16, sh + 16);
        cp16(BL[0] + (u32)tid * 32,      sl);
        cp16(BL[0] + (u32)tid * 32 + 16, sl + 16);
        cp_commit();
    }

    for (int t = 0; t < 16; ++t) {
        const int buf = t & 1;
        cp_wait0();

#pragma unroll
        for (int i = 0; i < 8; ++i) {
            const u32 sw = swz((u32)((xr + 16 * i) * 128 + xc4 * 8));
            u32 h01, h23, l01, l23;
            split4(ra[i], h01, h23, l01, l23);
            sts64(XH[buf] + sw, h01, h23);
            sts64(XL[buf] + sw, l01, l23);
        }
        __syncthreads();

        if (t + 1 < 16) {
            const u32 nb = BH[buf ^ 1], nl = BL[buf ^ 1];
            const char* sh = (const char*)g_Bh + (size_t)(kh * 16 + t + 1) * 8192 + tid * 32;
            const char* sl = (const char*)g_Bl + (size_t)(kh * 16 + t + 1) * 8192 + tid * 32;
            cp16(nb + (u32)tid * 32,      sh);
            cp16(nb + (u32)tid * 32 + 16, sh + 16);
            cp16(nl + (u32)tid * 32,      sl);
            cp16(nl + (u32)tid * 32 + 16, sl + 16);
            cp_commit();
            const int k0 = kbase + (t + 1) * KS;
#pragma unroll
            for (int i = 0; i < 8; ++i)
                ra[i] = *(const float4*)(x + (size_t)(n0 + xr + 16 * i) * EE + k0 + xc4 * 4);
        }

#pragma unroll
        for (int s = 0; s < 4; ++s) {
            const u32 xo = swz((u32)((m0 + (lane & 15)) * 128 + s * 32 + (lane >> 4) * 16));
            u32 a0, a1, a2, a3, f0, f1, f2, f3;
            ldsm4(a0, a1, a2, a3, XH[buf] + xo);
            ldsm4(f0, f1, f2, f3, XL[buf] + xo);

            u32 bh[4][4];
#pragma unroll
            for (int j = 0; j < 4; ++j) {
                const u32 bo_ = swz((u32)((16 * j + (lane & 15)) * 128 + s * 32 + (lane >> 4) * 16));
                ldsm4(bh[j][0], bh[j][1], bh[j][2], bh[j][3], BH[buf] + bo_);
            }
            // pass 1: Ah*Bh — 8 independent accumulator chains
#pragma unroll
            for (int j = 0; j < 4; ++j) {
                mma16816(acc[2 * j],     a0, a1, a2, a3, bh[j][0], bh[j][2]);
                mma16816(acc[2 * j + 1], a0, a1, a2, a3, bh[j][1], bh[j][3]);
            }
            // pass 2: Al*Bh
#pragma unroll
            for (int j = 0; j < 4; ++j) {
                mma16816(acc[2 * j],     f0, f1, f2, f3, bh[j][0], bh[j][2]);
                mma16816(acc[2 * j + 1], f0, f1, f2, f3, bh[j][1], bh[j][3]);
            }
            // pass 3: Ah*Bl
            u32 bl[4][4];
#pragma unroll
            for (int j = 0; j < 4; ++j) {
                const u32 bo_ = swz((u32)((16 * j + (lane & 15)) * 128 + s * 32 + (lane >> 4) * 16));
                ldsm4(bl[j][0], bl[j][1], bl[j][2], bl[j][3], BL[buf] + bo_);
            }
#pragma unroll
            for (int j = 0; j < 4; ++j) {
                mma16816(acc[2 * j],     a0, a1, a2, a3, bl[j][0], bl[j][2]);
                mma16816(acc[2 * j + 1], a0, a1, a2, a3, bl[j][1], bl[j][3]);
            }
        }
    }

    const int r0 = lane >> 2;
    const int cb = 2 * (lane & 3);
    const int na = n0 + m0 + r0;
    float* pa = g_mpart + ((size_t)kh * NTOK + na) * CC;
    float* pb = pa + 8 * CC;
#pragma unroll
    for (int nt = 0; nt < 8; ++nt) {
        const int c = 8 * nt + cb;
        *(float2*)(pa + c) = make_float2(acc[nt][0], acc[nt][1]);
        *(float2*)(pb + c) = make_float2(acc[nt][2], acc[nt][3]);
    }
}

// ---------------------------------------------------------------------------
// Combine (float4): out[p, t, c..c+3] = part0 + part1 + beta,  n = t*1024+p
// ---------------------------------------------------------------------------
__global__ void combine(float* __restrict__ out)
{
    const int e4 = blockIdx.x * 256 + threadIdx.x;   // 0 .. NTOK*CC/4-1
    const int n = e4 >> 4, c = (e4 & 15) * 4;
    const float4 a = *(const float4*)&g_mpart[(size_t)n * CC + c];
    const float4 b = *(const float4*)&g_mpart[(size_t)(NTOK + n) * CC + c];
    const float4 bb = *(const float4*)&g_beta[c];
    float4 w;
    w.x = a.x + b.x + bb.x; w.y = a.y + b.y + bb.y;
    w.z = a.z + b.z + bb.z; w.w = a.w + b.w + bb.w;
    const int p = n & 1023, t = n >> 10;
    *(float4*)&out[(size_t)p * (FF * CC) + t * CC + c] = w;
}

// ---------------------------------------------------------------------------
extern "C" void kernel_launch(void* const* d_in, const int* in_sizes, int n_in,
                              void* d_out, int out_size)
{
    (void)in_sizes; (void)n_in; (void)out_size;
    const float* emb = (const float*)d_in[0];
    const float* Wv  = (const float*)d_in[3];
    const float* bv  = (const float*)d_in[6];
    const float* Wo  = (const float*)d_in[7];
    const float* bo  = (const float*)d_in[8];
    const float* Wmp = (const float*)d_in[9];
    const float* bmp = (const float*)d_in[10];
    float* out = (float*)d_out;

    const int wg_smem = 65536 + 1024;
    const int mm_smem = 98304 + 1024;
    cudaFuncSetAttribute(wgemm, cudaFuncAttributeMaxDynamicSharedMemorySize, wg_smem);
    cudaFuncSetAttribute(main_mma_sk, cudaFuncAttributeMaxDynamicSharedMemorySize, mm_smem);

    // T1 = Wmp @ Wo (split-K over full chip), reduce
    wgemm<<<dim3(32, KCH), 256, wg_smem>>>(Wmp, Wo, 0);
    reduceK<<<128, 256>>>(0, nullptr, nullptr, nullptr, nullptr);
    // M = 0.75 * T1 @ Wv; reduce + bf16 split/swizzle + beta (fused parallel blocks)
    wgemm<<<dim3(32, KCH), 256, wg_smem>>>(nullptr, Wv, 1);
    reduceK<<<192, 256>>>(1, bv, bo, bmp, Wmp);

    // Main GEMM split-K (2 CTAs/SM) + combine epilogue
    main_mma_sk<<<dim3(144, 2), 256, mm_smem>>>(emb);
    combine<<<(NTOK * CC) / 4 / 256, 256>>>(out);
}

// round 14
// speedup vs baseline: 2.1089x; 1.1811x over previous
#include <cuda_runtime.h>
#include <cuda_bf16.h>
#include <cuda_fp16.h>
#include <cstdint>

#define EE   2048
#define CC   64
#define FF   18
#define NTOK 18432
#define KS   64
#define KCH  8       // split-K chunks in wgemm

typedef unsigned long long u64;
typedef unsigned int u32;

// Scratch (__device__ globals: allocation-free rule)
__device__ float g_part[KCH * CC * EE];                   // wgemm split-K partials (4 MB)
__device__ float g_mpart[2 * NTOK * CC];                  // main split-K partials (9.4 MB)
__device__ float g_T1[CC * EE];                           // Wmp @ Wo
__device__ __align__(16) float g_beta[CC];
__device__ __align__(16) unsigned char g_Bh[CC * EE * 2]; // M hi (fp16), pre-swizzled tiles
__device__ __align__(16) unsigned char g_Bl[CC * EE * 2]; // M lo (fp16), pre-swizzled tiles

// ---------------- helpers ----------------
__device__ __forceinline__ unsigned smem_u32(const void* p) {
    return (unsigned)__cvta_generic_to_shared(p);
}
__device__ __forceinline__ void cp16(unsigned s, const void* g) {
    asm volatile("cp.async.ca.shared.global [%0], [%1], 16;" :: "r"(s), "l"(g));
}
__device__ __forceinline__ void cp_commit() { asm volatile("cp.async.commit_group;"); }
__device__ __forceinline__ void cp_wait0()  { asm volatile("cp.async.wait_group 0;"); }
__device__ __forceinline__ void sts64(u32 a, u32 lo, u32 hi) {
    asm volatile("st.shared.v2.u32 [%0], {%1,%2};" :: "r"(a), "r"(lo), "r"(hi));
}
__device__ __forceinline__ void ldsm4(u32& r0, u32& r1, u32& r2, u32& r3, u32 a) {
    asm volatile("ldmatrix.sync.aligned.m8n8.x4.shared.b16 {%0,%1,%2,%3}, [%4];"
                 : "=r"(r0), "=r"(r1), "=r"(r2), "=r"(r3) : "r"(a));
}
__device__ __forceinline__ void ldsm4t(u32& r0, u32& r1, u32& r2, u32& r3, u32 a) {
    asm volatile("ldmatrix.sync.aligned.m8n8.x4.trans.shared.b16 {%0,%1,%2,%3}, [%4];"
                 : "=r"(r0), "=r"(r1), "=r"(r2), "=r"(r3) : "r"(a));
}
__device__ __forceinline__ void mma16816(float* c, u32 a0, u32 a1, u32 a2, u32 a3,
                                         u32 b0, u32 b1) {
    asm volatile("mma.sync.aligned.m16n8k16.row.col.f32.bf16.bf16.f32 "
                 "{%0,%1,%2,%3}, {%4,%5,%6,%7}, {%8,%9}, {%0,%1,%2,%3};"
                 : "+f"(c[0]), "+f"(c[1]), "+f"(c[2]), "+f"(c[3])
                 : "r"(a0), "r"(a1), "r"(a2), "r"(a3), "r"(b0), "r"(b1));
}
__device__ __forceinline__ void mma16816h(float* c, u32 a0, u32 a1, u32 a2, u32 a3,
                                          u32 b0, u32 b1) {
    asm volatile("mma.sync.aligned.m16n8k16.row.col.f32.f16.f16.f32 "
                 "{%0,%1,%2,%3}, {%4,%5,%6,%7}, {%8,%9}, {%0,%1,%2,%3};"
                 : "+f"(c[0]), "+f"(c[1]), "+f"(c[2]), "+f"(c[3])
                 : "r"(a0), "r"(a1), "r"(a2), "r"(a3), "r"(b0), "r"(b1));
}
__device__ __forceinline__ u32 swz(u32 off) { return off ^ ((off >> 3) & 0x70u); }

__device__ __forceinline__ void split4(float4 v, u32& h01, u32& h23, u32& l01, u32& l23) {
    asm("cvt.rn.bf16x2.f32 %0, %1, %2;" : "=r"(h01) : "f"(v.y), "f"(v.x));
    asm("cvt.rn.bf16x2.f32 %0, %1, %2;" : "=r"(h23) : "f"(v.w), "f"(v.z));
    float e0 = v.x - __uint_as_float(h01 << 16);
    float e1 = v.y - __uint_as_float(h01 & 0xffff0000u);
    float e2 = v.z - __uint_as_float(h23 << 16);
    float e3 = v.w - __uint_as_float(h23 & 0xffff0000u);
    asm("cvt.rn.bf16x2.f32 %0, %1, %2;" : "=r"(l01) : "f"(e1), "f"(e0));
    asm("cvt.rn.bf16x2.f32 %0, %1, %2;" : "=r"(l23) : "f"(e3), "f"(e2));
}

// ---------------------------------------------------------------------------
// wgemm (split-K, bf16 3-term) — unchanged (proven).
// ---------------------------------------------------------------------------
__global__ void __launch_bounds__(256, 2)
wgemm(const float* __restrict__ Aglob, const float* __restrict__ Bglob, int useT1)
{
    const float* A = useT1 ? g_T1 : Aglob;
    extern __shared__ char smraw[];
    const u32 base = (smem_u32(smraw) + 1023u) & ~1023u;
    const u32 AH[2]  = { base,          base + 8192u  };
    const u32 AL[2]  = { base + 16384u, base + 24576u };
    const u32 BSH[2] = { base + 32768u, base + 40960u };
    const u32 BSL[2] = { base + 49152u, base + 57344u };

    const int tid = threadIdx.x;
    const int wid = tid >> 5, lane = tid & 31;
    const int j0 = blockIdx.x * 64;
    const int kbase = blockIdx.y * 256;
    const int c0 = (wid & 3) * 16;
    const int jh = (wid >> 2) * 32;

    const int lr = tid >> 4;
    const int lc = tid & 15;

    float acc[4][4];
#pragma unroll
    for (int i = 0; i < 4; ++i)
#pragma unroll
        for (int j = 0; j < 4; ++j) acc[i][j] = 0.f;

    float4 rA[4], rB[4];
#pragma unroll
    for (int i = 0; i < 4; ++i) {
        rA[i] = *(const float4*)(A + (size_t)(lr + 16 * i) * EE + kbase + lc * 4);
        rB[i] = *(const float4*)(Bglob + (size_t)(kbase + lr + 16 * i) * EE + j0 + lc * 4);
    }

    for (int t = 0; t < 4; ++t) {
        const int buf = t & 1;
#pragma unroll
        for (int i = 0; i < 4; ++i) {
            const u32 sw = swz((u32)((lr + 16 * i) * 128 + lc * 8));
            u32 h01, h23, l01, l23;
            split4(rA[i], h01, h23, l01, l23);
            sts64(AH[buf] + sw, h01, h23);
            sts64(AL[buf] + sw, l01, l23);
            split4(rB[i], h01, h23, l01, l23);
            sts64(BSH[buf] + sw, h01, h23);
            sts64(BSL[buf] + sw, l01, l23);
        }
        __syncthreads();

        if (t + 1 < 4) {
            const int kc = kbase + (t + 1) * 64;
#pragma unroll
            for (int i = 0; i < 4; ++i) {
                rA[i] = *(const float4*)(A + (size_t)(lr + 16 * i) * EE + kc + lc * 4);
                rB[i] = *(const float4*)(Bglob + (size_t)(kc + lr + 16 * i) * EE + j0 + lc * 4);
            }
        }

        const int r = lane & 7, g = lane >> 3;
#pragma unroll
        for (int s = 0; s < 4; ++s) {
            const u32 asw = swz((u32)((c0 + (lane & 15)) * 128 + s * 32 + (lane >> 4) * 16));
            u32 a0, a1, a2, a3, f0, f1, f2, f3;
            ldsm4(a0, a1, a2, a3, AH[buf] + asw);
            ldsm4(f0, f1, f2, f3, AL[buf] + asw);
#pragma unroll
            for (int h = 0; h < 2; ++h) {
                const int jb = jh + h * 16;
                const u32 bsw = swz((u32)((s * 16 + (g >> 1) * 8 + r) * 128
                                          + (jb + (g & 1) * 8) * 2));
                u32 b0, b1, b2, b3, e0, e1, e2, e3;
                ldsm4t(b0, b1, b2, b3, BSH[buf] + bsw);
                ldsm4t(e0, e1, e2, e3, BSL[buf] + bsw);
                mma16816(acc[2 * h],     a0, a1, a2, a3, b0, b2);
                mma16816(acc[2 * h],     a0, a1, a2, a3, e0, e2);
                mma16816(acc[2 * h],     f0, f1, f2, f3, b0, b2);
                mma16816(acc[2 * h + 1], a0, a1, a2, a3, b1, b3);
                mma16816(acc[2 * h + 1], a0, a1, a2, a3, e1, e3);
                mma16816(acc[2 * h + 1], f0, f1, f2, f3, b1, b3);
            }
        }
        if (t + 1 < 4) __syncthreads();
    }

    const int r0 = lane >> 2;
    const int cb = 2 * (lane & 3);
    float* pbase = g_part + (size_t)blockIdx.y * (CC * EE);
#pragma unroll
    for (int nt = 0; nt < 4; ++nt) {
        const int j = j0 + jh + nt * 8 + cb;
        const int ca = c0 + r0, cbig = ca + 8;
        *(float2*)&pbase[(size_t)ca * EE + j]   = make_float2(acc[nt][0], acc[nt][1]);
        *(float2*)&pbase[(size_t)cbig * EE + j] = make_float2(acc[nt][2], acc[nt][3]);
    }
}

// ---------------------------------------------------------------------------
// reduceK: blocks 0..127 sum KCH split-K partials (float4 per thread).
//   which==0 -> g_T1 (fp32)
//   which==1 -> 0.75x, FP16 hi/lo exact split, pre-swizzled tiles.
// Mode 1 blocks 128..191: beta[c] = 0.75*(T1[c,:]@bv + Wmp[c,:]@bo) + bmp[c]
// ---------------------------------------------------------------------------
__global__ void reduceK(int which, const float* __restrict__ bv,
                        const float* __restrict__ bo, const float* __restrict__ bmp,
                        const float* __restrict__ Wmp)
{
    const int tid = threadIdx.x;
    if (blockIdx.x >= 128) {            // beta blocks (mode 1 only)
        __shared__ float red[256];
        const int c = blockIdx.x - 128;
        const float4* t1r = (const float4*)(g_T1 + (size_t)c * EE);
        const float4* wmr = (const float4*)(Wmp + (size_t)c * EE);
        const float4* bv4 = (const float4*)bv;
        const float4* bo4 = (const float4*)bo;
        float s = 0.f;
#pragma unroll
        for (int q = 0; q < 2; ++q) {
            const int i = tid + 256 * q;
            float4 a = t1r[i], b = bv4[i], d = wmr[i], e = bo4[i];
            s += a.x * b.x + a.y * b.y + a.z * b.z + a.w * b.w;
            s += d.x * e.x + d.y * e.y + d.z * e.z + d.w * e.w;
        }
        red[tid] = s;
        __syncthreads();
#pragma unroll
        for (int o = 128; o >= 32; o >>= 1) {
            if (tid < o) red[tid] += red[tid + o];
            __syncthreads();
        }
        if (tid < 32) {
            float v = red[tid];
#pragma unroll
            for (int o = 16; o; o >>= 1) v += __shfl_xor_sync(0xffffffffu, v, o);
            if (tid == 0) g_beta[c] = 0.75f * v + bmp[c];
        }
        return;
    }

    const int i4 = blockIdx.x * 256 + tid;  // 0 .. 32767
    float4 s = make_float4(0.f, 0.f, 0.f, 0.f);
#pragma unroll
    for (int q = 0; q < KCH; ++q) {
        float4 v = *(const float4*)&g_part[(size_t)q * (CC * EE) + i4 * 4];
        s.x += v.x; s.y += v.y; s.z += v.z; s.w += v.w;
    }
    if (which == 0) {
        *(float4*)&g_T1[i4 * 4] = s;
    } else {
        s.x *= 0.75f; s.y *= 0.75f; s.z *= 0.75f; s.w *= 0.75f;
        // fp16 hi/lo exact split
        __half h0 = __float2half_rn(s.x), h1 = __float2half_rn(s.y);
        __half h2 = __float2half_rn(s.z), h3 = __float2half_rn(s.w);
        __half l0 = __float2half_rn(s.x - __half2float(h0));
        __half l1 = __float2half_rn(s.y - __half2float(h1));
        __half l2 = __float2half_rn(s.z - __half2float(h2));
        __half l3 = __float2half_rn(s.w - __half2float(h3));
        __half2 H01 = __halves2half2(h0, h1), H23 = __halves2half2(h2, h3);
        __half2 L01 = __halves2half2(l0, l1), L23 = __halves2half2(l2, l3);
        const int i = i4 * 4;
        const int c = i >> 11, k = i & 2047;
        const int stage = k >> 6, kk = k & 63;
        const u32 sw = swz((u32)(c * 128 + kk * 2));
        *(u32*)(g_Bh + (size_t)stage * 8192 + sw)     = *(u32*)&H01;
        *(u32*)(g_Bh + (size_t)stage * 8192 + sw + 4) = *(u32*)&H23;
        *(u32*)(g_Bl + (size_t)stage * 8192 + sw)     = *(u32*)&L01;
        *(u32*)(g_Bl + (size_t)stage * 8192 + sw + 4) = *(u32*)&L23;
    }
}

// ---------------------------------------------------------------------------
// Main GEMM fp16 2-term split-K: grid (144 token-tiles, 2 k-halves), occ 2.
// X as SINGLE fp16 (rounding residual 2.1e-4 global rel, dominates final err);
// M as exact fp16 hi+lo pair.  out += Xh*Mh + Xh*Ml  -> 64 MMA/stage (vs 96).
// ---------------------------------------------------------------------------
__global__ void __launch_bounds__(256, 2)
main_mma_sk(const float* __restrict__ x)
{
    extern __shared__ char smraw[];
    const u32 base = (smem_u32(smraw) + 1023u) & ~1023u;
    const u32 XH[2] = { base,          base + 16384u };
    const u32 BH[2] = { base + 32768u, base + 40960u };
    const u32 BL[2] = { base + 49152u, base + 57344u };

    const int tid = threadIdx.x;
    const int wid = tid >> 5, lane = tid & 31;
    const int n0 = blockIdx.x * 128;
    const int kh = blockIdx.y;
    const int kbase = kh * 1024;
    const int m0 = wid * 16;

    float acc[8][4];
#pragma unroll
    for (int i = 0; i < 8; ++i)
#pragma unroll
        for (int j = 0; j < 4; ++j) acc[i][j] = 0.f;

    const int xr = tid >> 4, xc4 = tid & 15;

    float4 ra[8];
#pragma unroll
    for (int i = 0; i < 8; ++i)
        ra[i] = *(const float4*)(x + (size_t)(n0 + xr + 16 * i) * EE + kbase + xc4 * 4);
    {
        const char* sh = (const char*)g_Bh + (size_t)(kh * 16) * 8192 + tid * 32;
        const char* sl = (const char*)g_Bl + (size_t)(kh * 16) * 8192 + tid * 32;
        cp16(BH[0] + (u32)tid * 32,      sh);
        cp16(BH[0] + (u32)tid * 32 + 16, sh + 16);
        cp16(BL[0] + (u32)tid * 32,      sl);
        cp16(BL[0] + (u32)tid * 32 + 16, sl + 16);
        cp_commit();
    }

    for (int t = 0; t < 16; ++t) {
        const int buf = t & 1;
        cp_wait0();

        // convert X chunk t -> fp16 (single term), store swizzled
#pragma unroll
        for (int i = 0; i < 8; ++i) {
            const u32 sw = swz((u32)((xr + 16 * i) * 128 + xc4 * 8));
            float4 v = ra[i];
            __half2 H01 = __floats2half2_rn(v.x, v.y);
            __half2 H23 = __floats2half2_rn(v.z, v.w);
            sts64(sw + XH[buf], *(u32*)&H01, *(u32*)&H23);
        }
        __syncthreads();

        if (t + 1 < 16) {
            const u32 nb = BH[buf ^ 1], nl = BL[buf ^ 1];
            const char* sh = (const char*)g_Bh + (size_t)(kh * 16 + t + 1) * 8192 + tid * 32;
            const char* sl = (const char*)g_Bl + (size_t)(kh * 16 + t + 1) * 8192 + tid * 32;
            cp16(nb + (u32)tid * 32,      sh);
            cp16(nb + (u32)tid * 32 + 16, sh + 16);
            cp16(nl + (u32)tid * 32,      sl);
            cp16(nl + (u32)tid * 32 + 16, sl + 16);
            cp_commit();
            const int k0 = kbase + (t + 1) * KS;
#pragma unroll
            for (int i = 0; i < 8; ++i)
                ra[i] = *(const float4*)(x + (size_t)(n0 + xr + 16 * i) * EE + k0 + xc4 * 4);
        }

#pragma unroll
        for (int s = 0; s < 4; ++s) {
            const u32 xo = swz((u32)((m0 + (lane & 15)) * 128 + s * 32 + (lane >> 4) * 16));
            u32 a0, a1, a2, a3;
            ldsm4(a0, a1, a2, a3, XH[buf] + xo);

            u32 bh[4][4];
#pragma unroll
            for (int j = 0; j < 4; ++j) {
                const u32 bo_ = swz((u32)((16 * j + (lane & 15)) * 128 + s * 32 + (lane >> 4) * 16));
                ldsm4(bh[j][0], bh[j][1], bh[j][2], bh[j][3], BH[buf] + bo_);
            }
            // pass 1: Xh*Mh — 8 independent accumulator chains
#pragma unroll
            for (int j = 0; j < 4; ++j) {
                mma16816h(acc[2 * j],     a0, a1, a2, a3, bh[j][0], bh[j][2]);
                mma16816h(acc[2 * j + 1], a0, a1, a2, a3, bh[j][1], bh[j][3]);
            }
            // pass 2: Xh*Ml
            u32 bl[4][4];
#pragma unroll
            for (int j = 0; j < 4; ++j) {
                const u32 bo_ = swz((u32)((16 * j + (lane & 15)) * 128 + s * 32 + (lane >> 4) * 16));
                ldsm4(bl[j][0], bl[j][1], bl[j][2], bl[j][3], BL[buf] + bo_);
            }
#pragma unroll
            for (int j = 0; j < 4; ++j) {
                mma16816h(acc[2 * j],     a0, a1, a2, a3, bl[j][0], bl[j][2]);
                mma16816h(acc[2 * j + 1], a0, a1, a2, a3, bl[j][1], bl[j][3]);
            }
        }
    }

    const int r0 = lane >> 2;
    const int cb = 2 * (lane & 3);
    const int na = n0 + m0 + r0;
    float* pa = g_mpart + ((size_t)kh * NTOK + na) * CC;
    float* pb = pa + 8 * CC;
#pragma unroll
    for (int nt = 0; nt < 8; ++nt) {
        const int c = 8 * nt + cb;
        *(float2*)(pa + c) = make_float2(acc[nt][0], acc[nt][1]);
        *(float2*)(pb + c) = make_float2(acc[nt][2], acc[nt][3]);
    }
}

// ---------------------------------------------------------------------------
// Combine (float4): out[p, t, c..c+3] = part0 + part1 + beta,  n = t*1024+p
// ---------------------------------------------------------------------------
__global__ void combine(float* __restrict__ out)
{
    const int e4 = blockIdx.x * 256 + threadIdx.x;   // 0 .. NTOK*CC/4-1
    const int n = e4 >> 4, c = (e4 & 15) * 4;
    const float4 a = *(const float4*)&g_mpart[(size_t)n * CC + c];
    const float4 b = *(const float4*)&g_mpart[(size_t)(NTOK + n) * CC + c];
    const float4 bb = *(const float4*)&g_beta[c];
    float4 w;
    w.x = a.x + b.x + bb.x; w.y = a.y + b.y + bb.y;
    w.z = a.z + b.z + bb.z; w.w = a.w + b.w + bb.w;
    const int p = n & 1023, t = n >> 10;
    *(float4*)&out[(size_t)p * (FF * CC) + t * CC + c] = w;
}

// ---------------------------------------------------------------------------
extern "C" void kernel_launch(void* const* d_in, const int* in_sizes, int n_in,
                              void* d_out, int out_size)
{
    (void)in_sizes; (void)n_in; (void)out_size;
    const float* emb = (const float*)d_in[0];
    const float* Wv  = (const float*)d_in[3];
    const float* bv  = (const float*)d_in[6];
    const float* Wo  = (const float*)d_in[7];
    const float* bo  = (const float*)d_in[8];
    const float* Wmp = (const float*)d_in[9];
    const float* bmp = (const float*)d_in[10];
    float* out = (float*)d_out;

    const int wg_smem = 65536 + 1024;
    const int mm_smem = 65536 + 1024;
    cudaFuncSetAttribute(wgemm, cudaFuncAttributeMaxDynamicSharedMemorySize, wg_smem);
    cudaFuncSetAttribute(main_mma_sk, cudaFuncAttributeMaxDynamicSharedMemorySize, mm_smem);

    // T1 = Wmp @ Wo (split-K over full chip), reduce
    wgemm<<<dim3(32, KCH), 256, wg_smem>>>(Wmp, Wo, 0);
    reduceK<<<128, 256>>>(0, nullptr, nullptr, nullptr, nullptr);
    // M = 0.75 * T1 @ Wv; reduce + fp16 hi/lo split/swizzle + beta (fused)
    wgemm<<<dim3(32, KCH), 256, wg_smem>>>(nullptr, Wv, 1);
    reduceK<<<192, 256>>>(1, bv, bo, bmp, Wmp);

    // Main GEMM fp16 2-term split-K (2 CTAs/SM) + combine epilogue
    main_mma_sk<<<dim3(144, 2), 256, mm_smem>>>(emb);
    combine<<<(NTOK * CC) / 4 / 256, 256>>>(out);
}

// round 15
// speedup vs baseline: 2.4359x; 1.1550x over previous
#include <cuda_runtime.h>
#include <cuda_bf16.h>
#include <cuda_fp16.h>
#include <cstdint>

#define EE   2048
#define CC   64
#define FF   18
#define NTOK 18432
#define KS   64
#define KCH  8       // split-K chunks in wgemm

typedef unsigned long long u64;
typedef unsigned int u32;

// Scratch (__device__ globals: allocation-free rule)
__device__ float g_part[KCH * CC * EE];                   // wgemm split-K partials (4 MB)
__device__ float g_mpart[2 * NTOK * CC];                  // main split-K partials (9.4 MB)
__device__ float g_T1[CC * EE];                           // Wmp @ Wo
__device__ __align__(16) float g_beta[CC];
__device__ __align__(16) unsigned char g_Bh[CC * EE * 2]; // M (fp16), pre-swizzled tiles

// ---------------- helpers ----------------
__device__ __forceinline__ unsigned smem_u32(const void* p) {
    return (unsigned)__cvta_generic_to_shared(p);
}
__device__ __forceinline__ void cp16(unsigned s, const void* g) {
    asm volatile("cp.async.ca.shared.global [%0], [%1], 16;" :: "r"(s), "l"(g));
}
__device__ __forceinline__ void cp_commit() { asm volatile("cp.async.commit_group;"); }
__device__ __forceinline__ void cp_wait0()  { asm volatile("cp.async.wait_group 0;"); }
__device__ __forceinline__ void sts64(u32 a, u32 lo, u32 hi) {
    asm volatile("st.shared.v2.u32 [%0], {%1,%2};" :: "r"(a), "r"(lo), "r"(hi));
}
__device__ __forceinline__ void ldsm4(u32& r0, u32& r1, u32& r2, u32& r3, u32 a) {
    asm volatile("ldmatrix.sync.aligned.m8n8.x4.shared.b16 {%0,%1,%2,%3}, [%4];"
                 : "=r"(r0), "=r"(r1), "=r"(r2), "=r"(r3) : "r"(a));
}
__device__ __forceinline__ void ldsm4t(u32& r0, u32& r1, u32& r2, u32& r3, u32 a) {
    asm volatile("ldmatrix.sync.aligned.m8n8.x4.trans.shared.b16 {%0,%1,%2,%3}, [%4];"
                 : "=r"(r0), "=r"(r1), "=r"(r2), "=r"(r3) : "r"(a));
}
__device__ __forceinline__ void mma16816(float* c, u32 a0, u32 a1, u32 a2, u32 a3,
                                         u32 b0, u32 b1) {
    asm volatile("mma.sync.aligned.m16n8k16.row.col.f32.bf16.bf16.f32 "
                 "{%0,%1,%2,%3}, {%4,%5,%6,%7}, {%8,%9}, {%0,%1,%2,%3};"
                 : "+f"(c[0]), "+f"(c[1]), "+f"(c[2]), "+f"(c[3])
                 : "r"(a0), "r"(a1), "r"(a2), "r"(a3), "r"(b0), "r"(b1));
}
__device__ __forceinline__ void mma16816h(float* c, u32 a0, u32 a1, u32 a2, u32 a3,
                                          u32 b0, u32 b1) {
    asm volatile("mma.sync.aligned.m16n8k16.row.col.f32.f16.f16.f32 "
                 "{%0,%1,%2,%3}, {%4,%5,%6,%7}, {%8,%9}, {%0,%1,%2,%3};"
                 : "+f"(c[0]), "+f"(c[1]), "+f"(c[2]), "+f"(c[3])
                 : "r"(a0), "r"(a1), "r"(a2), "r"(a3), "r"(b0), "r"(b1));
}
__device__ __forceinline__ u32 swz(u32 off) { return off ^ ((off >> 3) & 0x70u); }

__device__ __forceinline__ void split4(float4 v, u32& h01, u32& h23, u32& l01, u32& l23) {
    asm("cvt.rn.bf16x2.f32 %0, %1, %2;" : "=r"(h01) : "f"(v.y), "f"(v.x));
    asm("cvt.rn.bf16x2.f32 %0, %1, %2;" : "=r"(h23) : "f"(v.w), "f"(v.z));
    float e0 = v.x - __uint_as_float(h01 << 16);
    float e1 = v.y - __uint_as_float(h01 & 0xffff0000u);
    float e2 = v.z - __uint_as_float(h23 << 16);
    float e3 = v.w - __uint_as_float(h23 & 0xffff0000u);
    asm("cvt.rn.bf16x2.f32 %0, %1, %2;" : "=r"(l01) : "f"(e1), "f"(e0));
    asm("cvt.rn.bf16x2.f32 %0, %1, %2;" : "=r"(l23) : "f"(e3), "f"(e2));
}

// ---------------------------------------------------------------------------
// wgemm (split-K, bf16 3-term) — unchanged (proven; keeps M accurate in fp32).
// ---------------------------------------------------------------------------
__global__ void __launch_bounds__(256, 2)
wgemm(const float* __restrict__ Aglob, const float* __restrict__ Bglob, int useT1)
{
    const float* A = useT1 ? g_T1 : Aglob;
    extern __shared__ char smraw[];
    const u32 base = (smem_u32(smraw) + 1023u) & ~1023u;
    const u32 AH[2]  = { base,          base + 8192u  };
    const u32 AL[2]  = { base + 16384u, base + 24576u };
    const u32 BSH[2] = { base + 32768u, base + 40960u };
    const u32 BSL[2] = { base + 49152u, base + 57344u };

    const int tid = threadIdx.x;
    const int wid = tid >> 5, lane = tid & 31;
    const int j0 = blockIdx.x * 64;
    const int kbase = blockIdx.y * 256;
    const int c0 = (wid & 3) * 16;
    const int jh = (wid >> 2) * 32;

    const int lr = tid >> 4;
    const int lc = tid & 15;

    float acc[4][4];
#pragma unroll
    for (int i = 0; i < 4; ++i)
#pragma unroll
        for (int j = 0; j < 4; ++j) acc[i][j] = 0.f;

    float4 rA[4], rB[4];
#pragma unroll
    for (int i = 0; i < 4; ++i) {
        rA[i] = *(const float4*)(A + (size_t)(lr + 16 * i) * EE + kbase + lc * 4);
        rB[i] = *(const float4*)(Bglob + (size_t)(kbase + lr + 16 * i) * EE + j0 + lc * 4);
    }

    for (int t = 0; t < 4; ++t) {
        const int buf = t & 1;
#pragma unroll
        for (int i = 0; i < 4; ++i) {
            const u32 sw = swz((u32)((lr + 16 * i) * 128 + lc * 8));
            u32 h01, h23, l01, l23;
            split4(rA[i], h01, h23, l01, l23);
            sts64(AH[buf] + sw, h01, h23);
            sts64(AL[buf] + sw, l01, l23);
            split4(rB[i], h01, h23, l01, l23);
            sts64(BSH[buf] + sw, h01, h23);
            sts64(BSL[buf] + sw, l01, l23);
        }
        __syncthreads();

        if (t + 1 < 4) {
            const int kc = kbase + (t + 1) * 64;
#pragma unroll
            for (int i = 0; i < 4; ++i) {
                rA[i] = *(const float4*)(A + (size_t)(lr + 16 * i) * EE + kc + lc * 4);
                rB[i] = *(const float4*)(Bglob + (size_t)(kc + lr + 16 * i) * EE + j0 + lc * 4);
            }
        }

        const int r = lane & 7, g = lane >> 3;
#pragma unroll
        for (int s = 0; s < 4; ++s) {
            const u32 asw = swz((u32)((c0 + (lane & 15)) * 128 + s * 32 + (lane >> 4) * 16));
            u32 a0, a1, a2, a3, f0, f1, f2, f3;
            ldsm4(a0, a1, a2, a3, AH[buf] + asw);
            ldsm4(f0, f1, f2, f3, AL[buf] + asw);
#pragma unroll
            for (int h = 0; h < 2; ++h) {
                const int jb = jh + h * 16;
                const u32 bsw = swz((u32)((s * 16 + (g >> 1) * 8 + r) * 128
                                          + (jb + (g & 1) * 8) * 2));
                u32 b0, b1, b2, b3, e0, e1, e2, e3;
                ldsm4t(b0, b1, b2, b3, BSH[buf] + bsw);
                ldsm4t(e0, e1, e2, e3, BSL[buf] + bsw);
                mma16816(acc[2 * h],     a0, a1, a2, a3, b0, b2);
                mma16816(acc[2 * h],     a0, a1, a2, a3, e0, e2);
                mma16816(acc[2 * h],     f0, f1, f2, f3, b0, b2);
                mma16816(acc[2 * h + 1], a0, a1, a2, a3, b1, b3);
                mma16816(acc[2 * h + 1], a0, a1, a2, a3, e1, e3);
                mma16816(acc[2 * h + 1], f0, f1, f2, f3, b1, b3);
            }
        }
        if (t + 1 < 4) __syncthreads();
    }

    const int r0 = lane >> 2;
    const int cb = 2 * (lane & 3);
    float* pbase = g_part + (size_t)blockIdx.y * (CC * EE);
#pragma unroll
    for (int nt = 0; nt < 4; ++nt) {
        const int j = j0 + jh + nt * 8 + cb;
        const int ca = c0 + r0, cbig = ca + 8;
        *(float2*)&pbase[(size_t)ca * EE + j]   = make_float2(acc[nt][0], acc[nt][1]);
        *(float2*)&pbase[(size_t)cbig * EE + j] = make_float2(acc[nt][2], acc[nt][3]);
    }
}

// ---------------------------------------------------------------------------
// reduceK: blocks 0..127 sum KCH split-K partials (float4 per thread).
//   which==0 -> g_T1 (fp32)
//   which==1 -> 0.75x, single fp16, pre-swizzled tiles.
// Mode 1 blocks 128..191: beta[c] = 0.75*(T1[c,:]@bv + Wmp[c,:]@bo) + bmp[c]
// ---------------------------------------------------------------------------
__global__ void reduceK(int which, const float* __restrict__ bv,
                        const float* __restrict__ bo, const float* __restrict__ bmp,
                        const float* __restrict__ Wmp)
{
    const int tid = threadIdx.x;
    if (blockIdx.x >= 128) {            // beta blocks (mode 1 only)
        __shared__ float red[256];
        const int c = blockIdx.x - 128;
        const float4* t1r = (const float4*)(g_T1 + (size_t)c * EE);
        const float4* wmr = (const float4*)(Wmp + (size_t)c * EE);
        const float4* bv4 = (const float4*)bv;
        const float4* bo4 = (const float4*)bo;
        float s = 0.f;
#pragma unroll
        for (int q = 0; q < 2; ++q) {
            const int i = tid + 256 * q;
            float4 a = t1r[i], b = bv4[i], d = wmr[i], e = bo4[i];
            s += a.x * b.x + a.y * b.y + a.z * b.z + a.w * b.w;
            s += d.x * e.x + d.y * e.y + d.z * e.z + d.w * e.w;
        }
        red[tid] = s;
        __syncthreads();
#pragma unroll
        for (int o = 128; o >= 32; o >>= 1) {
            if (tid < o) red[tid] += red[tid + o];
            __syncthreads();
        }
        if (tid < 32) {
            float v = red[tid];
#pragma unroll
            for (int o = 16; o; o >>= 1) v += __shfl_xor_sync(0xffffffffu, v, o);
            if (tid == 0) g_beta[c] = 0.75f * v + bmp[c];
        }
        return;
    }

    const int i4 = blockIdx.x * 256 + tid;  // 0 .. 32767
    float4 s = make_float4(0.f, 0.f, 0.f, 0.f);
#pragma unroll
    for (int q = 0; q < KCH; ++q) {
        float4 v = *(const float4*)&g_part[(size_t)q * (CC * EE) + i4 * 4];
        s.x += v.x; s.y += v.y; s.z += v.z; s.w += v.w;
    }
    if (which == 0) {
        *(float4*)&g_T1[i4 * 4] = s;
    } else {
        s.x *= 0.75f; s.y *= 0.75f; s.z *= 0.75f; s.w *= 0.75f;
        __half2 H01 = __floats2half2_rn(s.x, s.y);
        __half2 H23 = __floats2half2_rn(s.z, s.w);
        const int i = i4 * 4;
        const int c = i >> 11, k = i & 2047;
        const int stage = k >> 6, kk = k & 63;
        const u32 sw = swz((u32)(c * 128 + kk * 2));
        *(u32*)(g_Bh + (size_t)stage * 8192 + sw)     = *(u32*)&H01;
        *(u32*)(g_Bh + (size_t)stage * 8192 + sw + 4) = *(u32*)&H23;
    }
}

// ---------------------------------------------------------------------------
// Main GEMM pure fp16 1-term split-K: grid (144, 2), 256 threads, occ 2.
// out += fp16(X) * fp16(M): 32 MMA/stage; HBM X-read becomes the floor.
// ---------------------------------------------------------------------------
__global__ void __launch_bounds__(256, 2)
main_mma_sk(const float* __restrict__ x)
{
    extern __shared__ char smraw[];
    const u32 base = (smem_u32(smraw) + 1023u) & ~1023u;
    const u32 XH[2] = { base,          base + 16384u };
    const u32 BH[2] = { base + 32768u, base + 40960u };

    const int tid = threadIdx.x;
    const int wid = tid >> 5, lane = tid & 31;
    const int n0 = blockIdx.x * 128;
    const int kh = blockIdx.y;
    const int kbase = kh * 1024;
    const int m0 = wid * 16;

    float acc[8][4];
#pragma unroll
    for (int i = 0; i < 8; ++i)
#pragma unroll
        for (int j = 0; j < 4; ++j) acc[i][j] = 0.f;

    const int xr = tid >> 4, xc4 = tid & 15;

    float4 ra[8];
#pragma unroll
    for (int i = 0; i < 8; ++i)
        ra[i] = *(const float4*)(x + (size_t)(n0 + xr + 16 * i) * EE + kbase + xc4 * 4);
    {
        const char* sh = (const char*)g_Bh + (size_t)(kh * 16) * 8192 + tid * 32;
        cp16(BH[0] + (u32)tid * 32,      sh);
        cp16(BH[0] + (u32)tid * 32 + 16, sh + 16);
        cp_commit();
    }

    for (int t = 0; t < 16; ++t) {
        const int buf = t & 1;
        cp_wait0();

        // convert X chunk t -> fp16, store swizzled
#pragma unroll
        for (int i = 0; i < 8; ++i) {
            const u32 sw = swz((u32)((xr + 16 * i) * 128 + xc4 * 8));
            float4 v = ra[i];
            __half2 H01 = __floats2half2_rn(v.x, v.y);
            __half2 H23 = __floats2half2_rn(v.z, v.w);
            sts64(sw + XH[buf], *(u32*)&H01, *(u32*)&H23);
        }
        __syncthreads();

        if (t + 1 < 16) {
            const char* sh = (const char*)g_Bh + (size_t)(kh * 16 + t + 1) * 8192 + tid * 32;
            cp16(BH[buf ^ 1] + (u32)tid * 32,      sh);
            cp16(BH[buf ^ 1] + (u32)tid * 32 + 16, sh + 16);
            cp_commit();
            const int k0 = kbase + (t + 1) * KS;
#pragma unroll
            for (int i = 0; i < 8; ++i)
                ra[i] = *(const float4*)(x + (size_t)(n0 + xr + 16 * i) * EE + k0 + xc4 * 4);
        }

#pragma unroll
        for (int s = 0; s < 4; ++s) {
            const u32 xo = swz((u32)((m0 + (lane & 15)) * 128 + s * 32 + (lane >> 4) * 16));
            u32 a0, a1, a2, a3;
            ldsm4(a0, a1, a2, a3, XH[buf] + xo);
#pragma unroll
            for (int j = 0; j < 4; ++j) {
                const u32 bo_ = swz((u32)((16 * j + (lane & 15)) * 128 + s * 32 + (lane >> 4) * 16));
                u32 b0, b1, b2, b3;
                ldsm4(b0, b1, b2, b3, BH[buf] + bo_);
                mma16816h(acc[2 * j],     a0, a1, a2, a3, b0, b2);
                mma16816h(acc[2 * j + 1], a0, a1, a2, a3, b1, b3);
            }
        }
    }

    const int r0 = lane >> 2;
    const int cb = 2 * (lane & 3);
    const int na = n0 + m0 + r0;
    float* pa = g_mpart + ((size_t)kh * NTOK + na) * CC;
    float* pb = pa + 8 * CC;
#pragma unroll
    for (int nt = 0; nt < 8; ++nt) {
        const int c = 8 * nt + cb;
        *(float2*)(pa + c) = make_float2(acc[nt][0], acc[nt][1]);
        *(float2*)(pb + c) = make_float2(acc[nt][2], acc[nt][3]);
    }
}

// ---------------------------------------------------------------------------
// Combine (float4): out[p, t, c..c+3] = part0 + part1 + beta,  n = t*1024+p
// ---------------------------------------------------------------------------
__global__ void combine(float* __restrict__ out)
{
    const int e4 = blockIdx.x * 256 + threadIdx.x;   // 0 .. NTOK*CC/4-1
    const int n = e4 >> 4, c = (e4 & 15) * 4;
    const float4 a = *(const float4*)&g_mpart[(size_t)n * CC + c];
    const float4 b = *(const float4*)&g_mpart[(size_t)(NTOK + n) * CC + c];
    const float4 bb = *(const float4*)&g_beta[c];
    float4 w;
    w.x = a.x + b.x + bb.x; w.y = a.y + b.y + bb.y;
    w.z = a.z + b.z + bb.z; w.w = a.w + b.w + bb.w;
    const int p = n & 1023, t = n >> 10;
    *(float4*)&out[(size_t)p * (FF * CC) + t * CC + c] = w;
}

// ---------------------------------------------------------------------------
extern "C" void kernel_launch(void* const* d_in, const int* in_sizes, int n_in,
                              void* d_out, int out_size)
{
    (void)in_sizes; (void)n_in; (void)out_size;
    const float* emb = (const float*)d_in[0];
    const float* Wv  = (const float*)d_in[3];
    const float* bv  = (const float*)d_in[6];
    const float* Wo  = (const float*)d_in[7];
    const float* bo  = (const float*)d_in[8];
    const float* Wmp = (const float*)d_in[9];
    const float* bmp = (const float*)d_in[10];
    float* out = (float*)d_out;

    const int wg_smem = 65536 + 1024;
    const int mm_smem = 49152 + 1024;
    cudaFuncSetAttribute(wgemm, cudaFuncAttributeMaxDynamicSharedMemorySize, wg_smem);
    cudaFuncSetAttribute(main_mma_sk, cudaFuncAttributeMaxDynamicSharedMemorySize, mm_smem);

    // T1 = Wmp @ Wo (split-K over full chip), reduce
    wgemm<<<dim3(32, KCH), 256, wg_smem>>>(Wmp, Wo, 0);
    reduceK<<<128, 256>>>(0, nullptr, nullptr, nullptr, nullptr);
    // M = 0.75 * T1 @ Wv; reduce + fp16 quantize/swizzle + beta (fused)
    wgemm<<<dim3(32, KCH), 256, wg_smem>>>(nullptr, Wv, 1);
    reduceK<<<192, 256>>>(1, bv, bo, bmp, Wmp);

    // Main GEMM pure fp16 1-term split-K (2 CTAs/SM) + combine epilogue
    main_mma_sk<<<dim3(144, 2), 256, mm_smem>>>(emb);
    combine<<<(NTOK * CC) / 4 / 256, 256>>>(out);
}